// round 9
// baseline (speedup 1.0000x reference)
#include <cuda_runtime.h>
#include <utility>
#include <cstdint>

// x[262144, 16] -> out[262144, 696]
// 696 = 16 identity + C(16,2)=120 pairs + C(16,3)=560 triples (lexicographic).
#define NC       16
#define N_OUT4   174      // 696 / 4 float4 per row
#define BLOCK    128      // threads per block == rows per block (4 warps)
#define CHUNK    8        // float4 columns staged per chunk
#define NCHUNK   22       // ceil(174 / 8); last chunk has 6 float4
#define RSTRIDE  36       // floats per staged row (32 data + 4 pad: conflict-free)

// 3-way column partition over chunks: [0,8) [8,15) [15,22)
#define P0_OFF   0
#define P0_N     8
#define P1_OFF   8
#define P1_N     7
#define P2_OFF   15
#define P2_N     7

// ---------------------------------------------------------------------------
// Compile-time subset index for output column c (lexicographic, matches
// itertools.combinations). j/k == -1 means "absent".
// ---------------------------------------------------------------------------
struct Idx3 { int i, j, k; };

__host__ __device__ constexpr Idx3 col_idx(int c) {
    if (c < NC) return Idx3{c, -1, -1};
    int p = NC;
    for (int i = 0; i < NC; i++)
        for (int j = i + 1; j < NC; j++) {
            if (c == p) return Idx3{i, j, -1};
            p++;
        }
    for (int i = 0; i < NC; i++)
        for (int j = i + 1; j < NC; j++)
            for (int k = j + 1; k < NC; k++) {
                if (c == p) return Idx3{i, j, k};
                p++;
            }
    return Idx3{0, 0, 0};
}

// Product for column C: all-register FMULs, indices folded at compile time.
template<int C>
__device__ __forceinline__ float val(const float* xv) {
    constexpr Idx3 t = col_idx(C);
    float v = xv[t.i];
    if constexpr (t.j >= 0) v *= xv[t.j];
    if constexpr (t.k >= 0) v *= xv[t.k];
    return v;
}

// Compute + stage this lane's row slice for chunk CH.
template<int CH, int... Is>
__device__ __forceinline__ void compute_chunk(const float* xv, float* lanerow,
                                              std::integer_sequence<int, Is...>) {
    ((*reinterpret_cast<float4*>(lanerow + Is * 4) =
          make_float4(val<(CH * CHUNK + Is) * 4 + 0>(xv),
                      val<(CH * CHUNK + Is) * 4 + 1>(xv),
                      val<(CH * CHUNK + Is) * 4 + 2>(xv),
                      val<(CH * CHUNK + Is) * 4 + 3>(xv))),
     ...);
}

// One chunk, fully warp-local: compute -> syncwarp -> transposed coalesced
// write-out (8-lane groups each cover one row's 8 float4 = 128B contiguous).
// Single-buffer WAR is safe: per-warp smem ops execute in program order.
template<int CH>
__device__ __forceinline__ void do_chunk(const float* xv, float* wbuf, float* lanerow,
                                         float4* out4, size_t wrow0, int lane) {
    constexpr int n4 = (CH == NCHUNK - 1) ? (N_OUT4 - CH * CHUNK) : CHUNK;
    compute_chunk<CH>(xv, lanerow, std::make_integer_sequence<int, n4>{});
    __syncwarp();

    const int c  = lane & 7;       // float4 column within chunk
    const int rb = lane >> 3;      // 0..3 row sub-group
    if (c < n4) {
        #pragma unroll
        for (int it = 0; it < 8; it++) {       // 4 rows per pass * 8 = 32 rows
            int r = it * 4 + rb;
            float4 v = *reinterpret_cast<const float4*>(wbuf + r * RSTRIDE + c * 4);
            __stcs(&out4[(wrow0 + r) * N_OUT4 + CH * CHUNK + c], v);
        }
    }
    __syncwarp();
}

// Run chunks OFF .. OFF+sizeof...(CHs)-1.
template<int OFF, int... CHs>
__device__ __forceinline__ void run_chunks(const float* xv, float* wbuf, float* lanerow,
                                           float4* out4, size_t wrow0, int lane,
                                           std::integer_sequence<int, CHs...>) {
    (do_chunk<OFF + CHs>(xv, wbuf, lanerow, out4, wrow0, lane), ...);
}

// 3-way column-split kernel: block (g,p) computes partition p's chunks for the
// 128 rows of group g. ~1/3 pair-product working set per block -> natural
// liveness ~70-90 regs, no forced cap needed (R7 showed hard caps spill).
__global__ __launch_bounds__(BLOCK)
void algebraic_kernel(const float* __restrict__ x, float* __restrict__ out)
{
    __shared__ float buf[BLOCK * RSTRIDE];   // 18,432 B (4 warp-private regions)

    const int tid  = threadIdx.x;
    const int lane = tid & 31;
    const int wid  = tid >> 5;

    const unsigned bid  = blockIdx.x;
    const unsigned grp  = bid / 3u;          // row group (mul-shift)
    const unsigned part = bid - grp * 3u;    // column partition 0/1/2

    const size_t wrow0 = (size_t)grp * BLOCK + wid * 32;  // warp's first row
    const size_t row   = wrow0 + lane;

    // Load this lane's row (warp reads 2KB contiguous, fully coalesced).
    // The 3 sibling blocks of a group read the same rows; L2 absorbs repeats.
    float xv[NC];
    const float4* xr = reinterpret_cast<const float4*>(x + row * NC);
    #pragma unroll
    for (int q = 0; q < 4; q++) {
        float4 v = __ldg(xr + q);
        xv[q * 4 + 0] = v.x;
        xv[q * 4 + 1] = v.y;
        xv[q * 4 + 2] = v.z;
        xv[q * 4 + 3] = v.w;
    }

    float* wbuf    = buf + wid * 32 * RSTRIDE;   // warp-private staging
    float* lanerow = wbuf + lane * RSTRIDE;
    float4* out4   = reinterpret_cast<float4*>(out);

    if (part == 0) {
        run_chunks<P0_OFF>(xv, wbuf, lanerow, out4, wrow0, lane,
                           std::make_integer_sequence<int, P0_N>{});
    } else if (part == 1) {
        run_chunks<P1_OFF>(xv, wbuf, lanerow, out4, wrow0, lane,
                           std::make_integer_sequence<int, P1_N>{});
    } else {
        run_chunks<P2_OFF>(xv, wbuf, lanerow, out4, wrow0, lane,
                           std::make_integer_sequence<int, P2_N>{});
    }
}

extern "C" void kernel_launch(void* const* d_in, const int* in_sizes, int n_in,
                              void* d_out, int out_size)
{
    const float* x = (const float*)d_in[0];
    float* out = (float*)d_out;

    int n_rows   = in_sizes[0] / NC;          // 262144
    int n_blocks = (n_rows / BLOCK) * 3;      // 6144 (x3 column split)

    algebraic_kernel<<<n_blocks, BLOCK>>>(x, out);
}

// round 10
// speedup vs baseline: 1.3748x; 1.3748x over previous
#include <cuda_runtime.h>
#include <utility>
#include <cstdint>

// x[262144, 16] -> out[262144, 696]
// 696 = 16 identity + C(16,2)=120 pairs + C(16,3)=560 triples (lexicographic).
#define NC       16
#define N_OUT4   174      // float4 per output row
#define BLOCK    128      // threads per block == rows per block (4 warps)
#define CHUNK    32       // float4 columns staged per chunk (512B bursts)
#define NCHUNK   6        // 5 full chunks + tail of 14
#define RSTRIDE  132      // floats per staged row (128 data + 4 pad: conflict-free)
#define SMEM_BYTES (BLOCK * RSTRIDE * 4)   // 67,584 B

// ---------------------------------------------------------------------------
// Compile-time subset index for output column c (lexicographic, matches
// itertools.combinations). j/k == -1 means "absent".
// ---------------------------------------------------------------------------
struct Idx3 { int i, j, k; };

__host__ __device__ constexpr Idx3 col_idx(int c) {
    if (c < NC) return Idx3{c, -1, -1};
    int p = NC;
    for (int i = 0; i < NC; i++)
        for (int j = i + 1; j < NC; j++) {
            if (c == p) return Idx3{i, j, -1};
            p++;
        }
    for (int i = 0; i < NC; i++)
        for (int j = i + 1; j < NC; j++)
            for (int k = j + 1; k < NC; k++) {
                if (c == p) return Idx3{i, j, k};
                p++;
            }
    return Idx3{0, 0, 0};
}

// Product for column C: all-register FMULs, indices folded at compile time.
template<int C>
__device__ __forceinline__ float val(const float* xv) {
    constexpr Idx3 t = col_idx(C);
    float v = xv[t.i];
    if constexpr (t.j >= 0) v *= xv[t.j];
    if constexpr (t.k >= 0) v *= xv[t.k];
    return v;
}

// Compute + stage this lane's row slice for chunk CH (STS interleaved with
// FMULs keeps the live set bounded).
template<int CH, int... Is>
__device__ __forceinline__ void compute_chunk(const float* xv, float* lanerow,
                                              std::integer_sequence<int, Is...>) {
    ((*reinterpret_cast<float4*>(lanerow + Is * 4) =
          make_float4(val<(CH * CHUNK + Is) * 4 + 0>(xv),
                      val<(CH * CHUNK + Is) * 4 + 1>(xv),
                      val<(CH * CHUNK + Is) * 4 + 2>(xv),
                      val<(CH * CHUNK + Is) * 4 + 3>(xv))),
     ...);
}

// One chunk, fully warp-local: compute -> syncwarp -> write-out where each
// iteration is ONE full-warp STG.128 covering one row's 512B contiguous
// segment (32 float4). 4x larger DRAM bursts than the 128B-segment scheme.
// Single-buffer WAR is safe: per-warp smem ops execute in program order.
template<int CH>
__device__ __forceinline__ void do_chunk(const float* xv, float* wbuf, float* lanerow,
                                         float4* out4, size_t wrow0, int lane) {
    constexpr int n4 = (CH == NCHUNK - 1) ? (N_OUT4 - CH * CHUNK) : CHUNK;
    compute_chunk<CH>(xv, lanerow, std::make_integer_sequence<int, n4>{});
    __syncwarp();

    if (lane < n4) {
        #pragma unroll
        for (int r = 0; r < 32; r++) {
            float4 v = *reinterpret_cast<const float4*>(wbuf + r * RSTRIDE + lane * 4);
            __stcs(&out4[(wrow0 + r) * N_OUT4 + CH * CHUNK + lane], v);
        }
    }
    __syncwarp();
}

template<int... CHs>
__device__ __forceinline__ void run_chunks(const float* xv, float* wbuf, float* lanerow,
                                           float4* out4, size_t wrow0, int lane,
                                           std::integer_sequence<int, CHs...>) {
    (do_chunk<CHs>(xv, wbuf, lanerow, out4, wrow0, lane), ...);
}

__global__ __launch_bounds__(BLOCK)
void algebraic_kernel(const float* __restrict__ x, float* __restrict__ out)
{
    extern __shared__ float buf[];           // 67,584 B (4 warp-private regions)

    const int tid  = threadIdx.x;
    const int lane = tid & 31;
    const int wid  = tid >> 5;

    const size_t wrow0 = (size_t)blockIdx.x * BLOCK + wid * 32;  // warp's first row
    const size_t row   = wrow0 + lane;

    // Load this lane's row (warp reads 2KB contiguous, fully coalesced).
    float xv[NC];
    const float4* xr = reinterpret_cast<const float4*>(x + row * NC);
    #pragma unroll
    for (int q = 0; q < 4; q++) {
        float4 v = __ldg(xr + q);
        xv[q * 4 + 0] = v.x;
        xv[q * 4 + 1] = v.y;
        xv[q * 4 + 2] = v.z;
        xv[q * 4 + 3] = v.w;
    }

    float* wbuf    = buf + wid * 32 * RSTRIDE;   // warp-private staging
    float* lanerow = wbuf + lane * RSTRIDE;

    run_chunks(xv, wbuf, lanerow, reinterpret_cast<float4*>(out),
               wrow0, lane, std::make_integer_sequence<int, NCHUNK>{});
}

extern "C" void kernel_launch(void* const* d_in, const int* in_sizes, int n_in,
                              void* d_out, int out_size)
{
    const float* x = (const float*)d_in[0];
    float* out = (float*)d_out;

    // Allow >48KB dynamic smem. Attribute set is not an allocation and is
    // legal during graph capture (idempotent, deterministic).
    cudaFuncSetAttribute(algebraic_kernel,
                         cudaFuncAttributeMaxDynamicSharedMemorySize, SMEM_BYTES);

    int n_rows   = in_sizes[0] / NC;      // 262144
    int n_blocks = n_rows / BLOCK;        // 2048

    algebraic_kernel<<<n_blocks, BLOCK, SMEM_BYTES>>>(x, out);
}